// round 1
// baseline (speedup 1.0000x reference)
#include <cuda_runtime.h>
#include <math.h>

// ---------------------------------------------------------------------------
// GVP MPNN layer. B=4, N=2048, K=30.
// h_V: [8192,148]  (v:[3,16] flat c*16+i at [0..48), s:[100] at [48..148))
// h_M: [8192,30,183] (v:[3,17] c*17+i at [0..51), s:[132] at [51..183))
// Pipeline:
//   K1 (persistent, weights in SMEM): per node, loop k: build h_EV,
//      GVP1(33v/232s -> 16v/100s), GVP2, GVP3(no act), mask, mean/30,
//      residual + GVP-LN1 -> g_hv
//   K2: GVP_dh1(16v/100s -> 32v/400s, act) -> g_t
//   K3: GVP_dh2(32v/400s -> 16v/100s, no act) + residual + LN2 + mask -> out
// ---------------------------------------------------------------------------

#define NT 256
constexpr int NODES = 4 * 2048;
constexpr int KNB   = 30;

__device__ float g_hv[NODES * 148];
__device__ float g_t [NODES * 496];

// Generic GVP on shared buffers. Layouts:
//  vcur: [3*NVI] (c*NVI+i), scat: input scalars [0..NSI), vn appended at [NSI..NSI+NH)
//  After call: vcur[0..3*NVO) = output vectors (gated if ACT),
//              scat[0..NSO)   = output scalars (relu'd if ACT)
template<int NVI,int NH,int NSI,int NSO,int NVO,bool ACT>
__device__ __forceinline__ void gvp_block(
    const float* __restrict__ Wh, const float* __restrict__ Ws,
    const float* __restrict__ Bs, const float* __restrict__ Wv,
    float* vcur, float* scat, float* vh, float* sred, float* vraw,
    float* gate, float* snew, int tid)
{
  // vh[c,h] = sum_i vcur[c,i] * Wh[i,h]
  for (int t = tid; t < 3 * NH; t += NT) {
    int c = t / NH, h = t - c * NH;
    float acc = 0.f;
    #pragma unroll
    for (int i = 0; i < NVI; ++i) acc += vcur[c * NVI + i] * Wh[i * NH + h];
    vh[t] = acc;
  }
  __syncthreads();
  // vn -> scat[NSI+h];  vraw[c,o] = sum_h vh[c,h]*Wv[h,o]
  for (int t = tid; t < NH + 3 * NVO; t += NT) {
    if (t < NH) {
      float a = vh[t], b = vh[NH + t], c = vh[2 * NH + t];
      scat[NSI + t] = sqrtf(fmaxf(a * a + b * b + c * c, 1e-8f));
    } else {
      int idx = t - NH; int c = idx / NVO, o = idx - c * NVO;
      float acc = 0.f;
      #pragma unroll
      for (int h = 0; h < NH; ++h) acc += vh[c * NH + h] * Wv[h * NVO + o];
      vraw[idx] = acc;
    }
  }
  __syncthreads();
  // s GEMM: 2-way split over input dim D per output
  constexpr int D  = NSI + NH;
  constexpr int H0 = D / 2;
  for (int t = tid; t < 2 * NSO; t += NT) {
    int o = t >> 1; int half = t & 1;
    int i0 = half ? H0 : 0;
    int i1 = half ? D  : H0;
    float acc = 0.f;
    const float* wp = Ws + o;
    #pragma unroll 4
    for (int i = i0; i < i1; ++i) acc += scat[i] * wp[i * NSO];
    sred[t] = acc;
  }
  __syncthreads();
  // combine + bias (+relu); gate = sigmoid(||vraw col||)
  for (int t = tid; t < NSO + (ACT ? NVO : 0); t += NT) {
    if (t < NSO) {
      float s = sred[2 * t] + sred[2 * t + 1] + Bs[t];
      if (ACT) s = fmaxf(s, 0.f);
      snew[t] = s;
    } else {
      int o = t - NSO;
      float a = vraw[o], b = vraw[NVO + o], c = vraw[2 * NVO + o];
      float n = sqrtf(fmaxf(a * a + b * b + c * c, 1e-8f));
      gate[o] = 1.f / (1.f + expf(-n));
    }
  }
  __syncthreads();
  // writeback into vcur / scat for next stage
  for (int t = tid; t < 3 * NVO + NSO; t += NT) {
    if (t < 3 * NVO) vcur[t] = ACT ? vraw[t] * gate[t % NVO] : vraw[t];
    else             scat[t - 3 * NVO] = snew[t - 3 * NVO];
  }
  __syncthreads();
}

// ------------------------------ K1: edges + mean + LN1 ---------------------
__global__ __launch_bounds__(NT, 1)
void k_edge(const float* __restrict__ hV, const float* __restrict__ hM,
            const int* __restrict__ maskA,
            const float* wh1, const float* ws1, const float* bs1, const float* wv1,
            const float* wh2, const float* ws2, const float* bs2, const float* wv2,
            const float* wh3, const float* ws3, const float* bs3, const float* wv3,
            const float* __restrict__ ln1g, const float* __restrict__ ln1b)
{
  extern __shared__ float sm[];
  float* WH1 = sm;            float* WS1 = WH1 + 1089;  float* WV1 = WS1 + 26500; float* BS1 = WV1 + 528;
  float* WH2 = BS1 + 100;     float* WS2 = WH2 + 256;   float* WV2 = WS2 + 11600; float* BS2 = WV2 + 256;
  float* WH3 = BS2 + 100;     float* WS3 = WH3 + 256;   float* WV3 = WS3 + 11600; float* BS3 = WV3 + 256;
  float* HS  = BS3 + 100;     float* DH  = HS + 148;    float* EB  = DH + 148;
  float* VCUR= EB + 183;      float* VH  = VCUR + 99;   float* SCAT= VH + 99;     float* SRED= SCAT + 265;
  float* VRAW= SRED + 200;    float* GATE= VRAW + 48;   float* SNEW= GATE + 16;   float* MISC= SNEW + 100;
  int tid = threadIdx.x;

  for (int i = tid; i < 1089;  i += NT) WH1[i] = wh1[i];
  for (int i = tid; i < 26500; i += NT) WS1[i] = ws1[i];
  for (int i = tid; i < 528;   i += NT) WV1[i] = wv1[i];
  for (int i = tid; i < 100;   i += NT) BS1[i] = bs1[i];
  for (int i = tid; i < 256;   i += NT) WH2[i] = wh2[i];
  for (int i = tid; i < 11600; i += NT) WS2[i] = ws2[i];
  for (int i = tid; i < 256;   i += NT) WV2[i] = wv2[i];
  for (int i = tid; i < 100;   i += NT) BS2[i] = bs2[i];
  for (int i = tid; i < 256;   i += NT) WH3[i] = wh3[i];
  for (int i = tid; i < 11600; i += NT) WS3[i] = ws3[i];
  for (int i = tid; i < 256;   i += NT) WV3[i] = wv3[i];
  for (int i = tid; i < 100;   i += NT) BS3[i] = bs3[i];
  __syncthreads();

  for (int node = blockIdx.x; node < NODES; node += gridDim.x) {
    for (int t = tid; t < 148; t += NT) { HS[t] = hV[node * 148 + t]; DH[t] = 0.f; }
    __syncthreads();

    for (int k = 0; k < KNB; ++k) {
      const float* ep = hM + (size_t)(node * KNB + k) * 183;
      for (int t = tid; t < 183; t += NT) EB[t] = ep[t];
      __syncthreads();
      // h_EV: v = [v_V(16), v_M(17)] per c; s = [s_V(100), s_M(132)]
      for (int t = tid; t < 99 + 232; t += NT) {
        if (t < 99) {
          int c = t / 33, i = t - c * 33;
          VCUR[t] = (i < 16) ? HS[c * 16 + i] : EB[c * 17 + (i - 16)];
        } else {
          int j = t - 99;
          SCAT[j] = (j < 100) ? HS[48 + j] : EB[51 + (j - 100)];
        }
      }
      __syncthreads();

      gvp_block<33, 33, 232, 100, 16, true >(WH1, WS1, BS1, WV1, VCUR, SCAT, VH, SRED, VRAW, GATE, SNEW, tid);
      gvp_block<16, 16, 100, 100, 16, true >(WH2, WS2, BS2, WV2, VCUR, SCAT, VH, SRED, VRAW, GATE, SNEW, tid);
      gvp_block<16, 16, 100, 100, 16, false>(WH3, WS3, BS3, WV3, VCUR, SCAT, VH, SRED, VRAW, GATE, SNEW, tid);

      float mk = (float)maskA[node * KNB + k];
      for (int t = tid; t < 148; t += NT)
        DH[t] += mk * (t < 48 ? VCUR[t] : SCAT[t - 48]);
      __syncthreads();
    }

    // x = h_V + mean_k(m); GVP-LayerNorm 1
    for (int t = tid; t < 148; t += NT) DH[t] = HS[t] + DH[t] * (1.f / KNB);
    __syncthreads();
    if (tid == 0) {
      float vm = 0.f;
      for (int i = 0; i < 16; ++i) {
        float a = DH[i], b = DH[16 + i], c = DH[32 + i];
        vm += fmaxf(a * a + b * b + c * c, 1e-8f);
      }
      MISC[0] = rsqrtf(vm * (1.f / 16.f));
      float mu = 0.f;
      for (int j = 0; j < 100; ++j) mu += DH[48 + j];
      mu *= 0.01f;
      float var = 0.f;
      for (int j = 0; j < 100; ++j) { float d = DH[48 + j] - mu; var += d * d; }
      var *= 0.01f;
      MISC[1] = mu; MISC[2] = rsqrtf(var + 1e-3f);
    }
    __syncthreads();
    for (int t = tid; t < 148; t += NT) {
      float v;
      if (t < 48) v = DH[t] * MISC[0];
      else { int j = t - 48; v = (DH[t] - MISC[1]) * MISC[2] * ln1g[j] + ln1b[j]; }
      g_hv[node * 148 + t] = v;
    }
    __syncthreads();
  }
}

// ------------------------------ K2: node GVP dh1 ---------------------------
__global__ __launch_bounds__(NT, 1)
void k_dh1(const float* wh, const float* ws, const float* bs, const float* wv)
{
  extern __shared__ float sm[];
  float* WH = sm;          float* WS = WH + 512;    float* BSH = WS + 52800; float* WV = BSH + 400;
  float* VCUR = WV + 1024; float* VH = VCUR + 96;   float* SCAT = VH + 96;   float* SRED = SCAT + 432;
  float* VRAW = SRED + 800;float* GATE = VRAW + 96; float* SNEW = GATE + 32;
  int tid = threadIdx.x;
  for (int i = tid; i < 512;   i += NT) WH[i]  = wh[i];
  for (int i = tid; i < 52800; i += NT) WS[i]  = ws[i];
  for (int i = tid; i < 400;   i += NT) BSH[i] = bs[i];
  for (int i = tid; i < 1024;  i += NT) WV[i]  = wv[i];
  __syncthreads();

  for (int node = blockIdx.x; node < NODES; node += gridDim.x) {
    for (int t = tid; t < 148; t += NT) {
      float v = g_hv[node * 148 + t];
      if (t < 48) VCUR[t] = v; else SCAT[t - 48] = v;
    }
    __syncthreads();
    gvp_block<16, 32, 100, 400, 32, true>(WH, WS, BSH, WV, VCUR, SCAT, VH, SRED, VRAW, GATE, SNEW, tid);
    for (int t = tid; t < 496; t += NT)
      g_t[node * 496 + t] = (t < 96) ? VCUR[t] : SCAT[t - 96];
    __syncthreads();
  }
}

// ------------------------------ K3: node GVP dh2 + LN2 + mask --------------
__global__ __launch_bounds__(NT, 1)
void k_dh2(const float* wh, const float* ws, const float* bs, const float* wv,
           const float* __restrict__ ln2g, const float* __restrict__ ln2b,
           const int* __restrict__ maskV, float* __restrict__ out)
{
  extern __shared__ float sm[];
  float* WH = sm;           float* WS = WH + 1024;  float* BSH = WS + 43200; float* WV = BSH + 100;
  float* HVB = WV + 512;    float* VCUR = HVB + 148;float* VH = VCUR + 96;   float* SCAT = VH + 96;
  float* SRED = SCAT + 432; float* VRAW = SRED + 200;float* GATE = VRAW + 48; float* SNEW = GATE + 16;
  float* MISC = SNEW + 100;
  int tid = threadIdx.x;
  for (int i = tid; i < 1024;  i += NT) WH[i]  = wh[i];
  for (int i = tid; i < 43200; i += NT) WS[i]  = ws[i];
  for (int i = tid; i < 100;   i += NT) BSH[i] = bs[i];
  for (int i = tid; i < 512;   i += NT) WV[i]  = wv[i];
  __syncthreads();

  for (int node = blockIdx.x; node < NODES; node += gridDim.x) {
    for (int t = tid; t < 148; t += NT) HVB[t] = g_hv[node * 148 + t];
    for (int t = tid; t < 496; t += NT) {
      float v = g_t[node * 496 + t];
      if (t < 96) VCUR[t] = v; else SCAT[t - 96] = v;
    }
    __syncthreads();
    gvp_block<32, 32, 400, 100, 16, false>(WH, WS, BSH, WV, VCUR, SCAT, VH, SRED, VRAW, GATE, SNEW, tid);
    for (int t = tid; t < 148; t += NT)
      HVB[t] += (t < 48) ? VCUR[t] : SCAT[t - 48];
    __syncthreads();
    if (tid == 0) {
      float vm = 0.f;
      for (int i = 0; i < 16; ++i) {
        float a = HVB[i], b = HVB[16 + i], c = HVB[32 + i];
        vm += fmaxf(a * a + b * b + c * c, 1e-8f);
      }
      MISC[0] = rsqrtf(vm * (1.f / 16.f));
      float mu = 0.f;
      for (int j = 0; j < 100; ++j) mu += HVB[48 + j];
      mu *= 0.01f;
      float var = 0.f;
      for (int j = 0; j < 100; ++j) { float d = HVB[48 + j] - mu; var += d * d; }
      var *= 0.01f;
      MISC[1] = mu; MISC[2] = rsqrtf(var + 1e-3f);
    }
    __syncthreads();
    float mk = (float)maskV[node];
    for (int t = tid; t < 148; t += NT) {
      float v;
      if (t < 48) v = HVB[t] * MISC[0];
      else { int j = t - 48; v = (HVB[t] - MISC[1]) * MISC[2] * ln2g[j] + ln2b[j]; }
      out[node * 148 + t] = mk * v;
    }
    __syncthreads();
  }
}

// ---------------------------------------------------------------------------
extern "C" void kernel_launch(void* const* d_in, const int* in_sizes, int n_in,
                              void* d_out, int out_size)
{
  const float* hV     = (const float*)d_in[0];
  const float* hM     = (const float*)d_in[1];
  const int*   maskV  = (const int*)  d_in[2];
  const int*   maskA  = (const int*)  d_in[3];
  const float* wev1_wh = (const float*)d_in[4];
  const float* wev1_ws = (const float*)d_in[5];
  const float* wev1_bs = (const float*)d_in[6];
  const float* wev1_wv = (const float*)d_in[7];
  const float* wev2_wh = (const float*)d_in[8];
  const float* wev2_ws = (const float*)d_in[9];
  const float* wev2_bs = (const float*)d_in[10];
  const float* wev2_wv = (const float*)d_in[11];
  const float* wev3_wh = (const float*)d_in[12];
  const float* wev3_ws = (const float*)d_in[13];
  const float* wev3_bs = (const float*)d_in[14];
  const float* wev3_wv = (const float*)d_in[15];
  const float* wdh1_wh = (const float*)d_in[16];
  const float* wdh1_ws = (const float*)d_in[17];
  const float* wdh1_bs = (const float*)d_in[18];
  const float* wdh1_wv = (const float*)d_in[19];
  const float* wdh2_wh = (const float*)d_in[20];
  const float* wdh2_ws = (const float*)d_in[21];
  const float* wdh2_bs = (const float*)d_in[22];
  const float* wdh2_wv = (const float*)d_in[23];
  const float* ln1g = (const float*)d_in[24];
  const float* ln1b = (const float*)d_in[25];
  const float* ln2g = (const float*)d_in[26];
  const float* ln2b = (const float*)d_in[27];
  float* out = (float*)d_out;

  int dev = 0; cudaGetDevice(&dev);
  int sms = 148;
  cudaDeviceGetAttribute(&sms, cudaDevAttrMultiProcessorCount, dev);

  // SMEM sizes (floats) matching the in-kernel layouts
  const size_t SM1 = (size_t)(52641 + 148 + 148 + 183 + 99 + 99 + 265 + 200 + 48 + 16 + 100 + 8) * sizeof(float);
  const size_t SM2 = (size_t)(54736 + 96 + 96 + 432 + 800 + 96 + 32 + 400) * sizeof(float);
  const size_t SM3 = (size_t)(44836 + 148 + 96 + 96 + 432 + 200 + 48 + 16 + 100 + 8) * sizeof(float);

  cudaFuncSetAttribute(k_edge, cudaFuncAttributeMaxDynamicSharedMemorySize, (int)SM1);
  cudaFuncSetAttribute(k_dh1,  cudaFuncAttributeMaxDynamicSharedMemorySize, (int)SM2);
  cudaFuncSetAttribute(k_dh2,  cudaFuncAttributeMaxDynamicSharedMemorySize, (int)SM3);

  k_edge<<<sms, NT, SM1>>>(hV, hM, maskA,
                           wev1_wh, wev1_ws, wev1_bs, wev1_wv,
                           wev2_wh, wev2_ws, wev2_bs, wev2_wv,
                           wev3_wh, wev3_ws, wev3_bs, wev3_wv,
                           ln1g, ln1b);
  k_dh1<<<sms, NT, SM2>>>(wdh1_wh, wdh1_ws, wdh1_bs, wdh1_wv);
  k_dh2<<<sms, NT, SM3>>>(wdh2_wh, wdh2_ws, wdh2_bs, wdh2_wv,
                          ln2g, ln2b, maskV, out);
}